// round 3
// baseline (speedup 1.0000x reference)
#include <cuda_runtime.h>

// Output = segment_sum(source[src_idx], seg_ids): softmax over the singleton
// axis is identically 1.0, so all attention machinery is dead code.
//
// Layout: one warp owns 128 consecutive edges. Half-warp 0 processes even
// edges, half-warp 1 odd edges; each lane holds 4 columns (float4), so one
// LDG.128 per half-warp fetches a full 256B source row. Indices are loaded
// as int4 (broadcast, 1 wavefront per 4 edges per array).
//
// Inputs: 0 source[N,64] f32, 2 src_idx[E] i32, 3 seg_ids[E] i32 (sorted).

#define EDGES_PER_WARP 128

__global__ void zero_out_kernel(float4* __restrict__ out4, int n4) {
    int i = blockIdx.x * blockDim.x + threadIdx.x;
    int stride = gridDim.x * blockDim.x;
    for (int j = i; j < n4; j += stride)
        out4[j] = make_float4(0.f, 0.f, 0.f, 0.f);
}

__device__ __forceinline__ void flush_acc(float* __restrict__ out, int cur,
                                          int colbase, float4 a) {
    float* p = out + (long long)cur * 64 + colbase;
    atomicAdd(p + 0, a.x);
    atomicAdd(p + 1, a.y);
    atomicAdd(p + 2, a.z);
    atomicAdd(p + 3, a.w);
}

__global__ void __launch_bounds__(256)
seg_gather_sum_kernel(const float4* __restrict__ src4,
                      const int4* __restrict__ src_idx4,
                      const int4* __restrict__ seg_ids4,
                      const int* __restrict__ src_idx,
                      const int* __restrict__ seg_ids,
                      float* __restrict__ out,
                      int E) {
    const int lane    = threadIdx.x & 31;
    const int half    = lane >> 4;        // 0: even edges, 1: odd edges
    const int sublane = lane & 15;        // owns columns [4*sublane, 4*sublane+4)
    const int colbase = sublane * 4;
    const int warp = blockIdx.x * (blockDim.x >> 5) + (threadIdx.x >> 5);

    int e0 = warp * EDGES_PER_WARP;
    if (e0 >= E) return;
    int e1 = e0 + EDGES_PER_WARP;
    if (e1 > E) e1 = E;

    // Main body: 4 edges per iteration (2 per half-warp). e0 is 128-aligned.
    int nquad = (e1 - e0) >> 2;           // number of full 4-edge groups
    int e = e0;

    int cur = -1;
    float4 acc = make_float4(0.f, 0.f, 0.f, 0.f);
    bool have = false;

    for (int q = 0; q < nquad; ++q, e += 4) {
        int4 s4 = __ldg(&seg_ids4[e >> 2]);
        int4 i4 = __ldg(&src_idx4[e >> 2]);

        // this half's two edges within the quad
        int sA = half ? s4.y : s4.x;
        int sB = half ? s4.w : s4.z;
        int iA = half ? i4.y : i4.x;
        int iB = half ? i4.w : i4.z;

        float4 vA = __ldg(&src4[(long long)iA * 16 + sublane]);
        float4 vB = __ldg(&src4[(long long)iB * 16 + sublane]);

        if (!have) { cur = sA; have = true; }

        if (sA != cur) {
            flush_acc(out, cur, colbase, acc);
            acc = make_float4(0.f, 0.f, 0.f, 0.f);
            cur = sA;
        }
        acc.x += vA.x; acc.y += vA.y; acc.z += vA.z; acc.w += vA.w;

        if (sB != cur) {
            flush_acc(out, cur, colbase, acc);
            acc = make_float4(0.f, 0.f, 0.f, 0.f);
            cur = sB;
        }
        acc.x += vB.x; acc.y += vB.y; acc.z += vB.z; acc.w += vB.w;
    }

    // Tail (only possible in the last warp if E % 4 != 0): half 0 handles all
    // remaining edges sequentially; half 1 contributes nothing further.
    if (half == 0) {
        for (; e < e1; ++e) {
            int s = __ldg(&seg_ids[e]);
            int idx = __ldg(&src_idx[e]);
            float4 v = __ldg(&src4[(long long)idx * 16 + sublane]);
            if (!have) { cur = s; have = true; }
            if (s != cur) {
                flush_acc(out, cur, colbase, acc);
                acc = make_float4(0.f, 0.f, 0.f, 0.f);
                cur = s;
            }
            acc.x += v.x; acc.y += v.y; acc.z += v.z; acc.w += v.w;
        }
    }

    if (have)
        flush_acc(out, cur, colbase, acc);
}

extern "C" void kernel_launch(void* const* d_in, const int* in_sizes, int n_in,
                              void* d_out, int out_size) {
    const float* source  = (const float*)d_in[0];
    const int*   src_idx = (const int*)d_in[2];
    const int*   seg_ids = (const int*)d_in[3];
    float* out = (float*)d_out;

    int E = in_sizes[2];

    // 1) zero the output (poisoned by harness; empty segments must be 0)
    int n4 = out_size / 4;
    int zthreads = 256;
    int zblocks = (n4 + zthreads - 1) / zthreads;
    if (zblocks > 1184) zblocks = 1184;
    zero_out_kernel<<<zblocks, zthreads>>>((float4*)d_out, n4);

    // 2) gather + segment-sum
    int nwarps = (E + EDGES_PER_WARP - 1) / EDGES_PER_WARP;
    int threads = 256;  // 8 warps
    int nblocks = (nwarps + 7) / 8;
    seg_gather_sum_kernel<<<nblocks, threads>>>(
        (const float4*)source, (const int4*)src_idx, (const int4*)seg_ids,
        src_idx, seg_ids, out, E);
}

// round 4
// speedup vs baseline: 1.3909x; 1.3909x over previous
#include <cuda_runtime.h>

// Output = segment_sum(source[src_idx], seg_ids): softmax over the singleton
// axis is identically 1.0, so all attention machinery is dead code.
//
// One warp owns 128 consecutive edges; lane owns 2 columns (float2), so one
// warp LDG.64 gather = one full 256B source row = 2 L2 lines. 8-deep unroll
// keeps 8 independent gathers (16 lines) in flight per warp. Indices read as
// int4 (2 per array per 8 edges). Sorted seg_ids -> running accumulator,
// flushed with atomicAdd on segment change (and once at chunk end).
//
// Inputs: 0 source[N,64] f32, 2 src_idx[E] i32, 3 seg_ids[E] i32 (sorted).

#define EDGES_PER_WARP 128

__global__ void zero_out_kernel(float4* __restrict__ out4, int n4) {
    int i = blockIdx.x * blockDim.x + threadIdx.x;
    int stride = gridDim.x * blockDim.x;
    for (int j = i; j < n4; j += stride)
        out4[j] = make_float4(0.f, 0.f, 0.f, 0.f);
}

__global__ void __launch_bounds__(256)
seg_gather_sum_kernel(const float2* __restrict__ src2,
                      const int4* __restrict__ src_idx4,
                      const int4* __restrict__ seg_ids4,
                      const int* __restrict__ src_idx,
                      const int* __restrict__ seg_ids,
                      float* __restrict__ out,
                      int E) {
    const int lane = threadIdx.x & 31;
    const int warp = blockIdx.x * (blockDim.x >> 5) + (threadIdx.x >> 5);
    int e0 = warp * EDGES_PER_WARP;
    if (e0 >= E) return;
    int e1 = e0 + EDGES_PER_WARP;
    if (e1 > E) e1 = E;

    int cur = seg_ids[e0];
    float ax = 0.f, ay = 0.f;

    int e = e0;
    int noct = (e1 - e0) >> 3;  // full 8-edge groups (e0 is 128-aligned)

#define ACC(S, V)                                                   \
    do {                                                            \
        if ((S) != cur) {                                           \
            atomicAdd(&out[(long long)cur * 64 + 2 * lane + 0], ax);\
            atomicAdd(&out[(long long)cur * 64 + 2 * lane + 1], ay);\
            ax = 0.f; ay = 0.f; cur = (S);                          \
        }                                                           \
        ax += (V).x; ay += (V).y;                                   \
    } while (0)

    for (int q = 0; q < noct; ++q, e += 8) {
        // --- batched loads: 4 index vectors + 8 independent gathers ---
        int4 sa = __ldg(&seg_ids4[(e >> 2) + 0]);
        int4 sb = __ldg(&seg_ids4[(e >> 2) + 1]);
        int4 ia = __ldg(&src_idx4[(e >> 2) + 0]);
        int4 ib = __ldg(&src_idx4[(e >> 2) + 1]);

        float2 v0 = __ldg(&src2[(long long)ia.x * 32 + lane]);
        float2 v1 = __ldg(&src2[(long long)ia.y * 32 + lane]);
        float2 v2 = __ldg(&src2[(long long)ia.z * 32 + lane]);
        float2 v3 = __ldg(&src2[(long long)ia.w * 32 + lane]);
        float2 v4 = __ldg(&src2[(long long)ib.x * 32 + lane]);
        float2 v5 = __ldg(&src2[(long long)ib.y * 32 + lane]);
        float2 v6 = __ldg(&src2[(long long)ib.z * 32 + lane]);
        float2 v7 = __ldg(&src2[(long long)ib.w * 32 + lane]);

        // --- accumulate / flush ---
        ACC(sa.x, v0);
        ACC(sa.y, v1);
        ACC(sa.z, v2);
        ACC(sa.w, v3);
        ACC(sb.x, v4);
        ACC(sb.y, v5);
        ACC(sb.z, v6);
        ACC(sb.w, v7);
    }

    // tail (only if E % 8 != 0 in the last chunk)
    for (; e < e1; ++e) {
        int s = __ldg(&seg_ids[e]);
        int idx = __ldg(&src_idx[e]);
        float2 v = __ldg(&src2[(long long)idx * 32 + lane]);
        ACC(s, v);
    }
#undef ACC

    // final flush
    atomicAdd(&out[(long long)cur * 64 + 2 * lane + 0], ax);
    atomicAdd(&out[(long long)cur * 64 + 2 * lane + 1], ay);
}

extern "C" void kernel_launch(void* const* d_in, const int* in_sizes, int n_in,
                              void* d_out, int out_size) {
    const float* source  = (const float*)d_in[0];
    const int*   src_idx = (const int*)d_in[2];
    const int*   seg_ids = (const int*)d_in[3];
    float* out = (float*)d_out;

    int E = in_sizes[2];

    // 1) zero the output (poisoned by harness; empty segments must be 0)
    int n4 = out_size / 4;
    int zthreads = 256;
    int zblocks = (n4 + zthreads - 1) / zthreads;
    if (zblocks > 1184) zblocks = 1184;
    zero_out_kernel<<<zblocks, zthreads>>>((float4*)d_out, n4);

    // 2) gather + segment-sum
    int nwarps = (E + EDGES_PER_WARP - 1) / EDGES_PER_WARP;
    int threads = 256;  // 8 warps
    int nblocks = (nwarps + 7) / 8;
    seg_gather_sum_kernel<<<nblocks, threads>>>(
        (const float2*)source, (const int4*)src_idx, (const int4*)seg_ids,
        src_idx, seg_ids, out, E);
}

// round 5
// speedup vs baseline: 1.4034x; 1.0090x over previous
#include <cuda_runtime.h>

// Output = segment_sum(source[src_idx], seg_ids): softmax over the singleton
// axis is identically 1.0, so all attention machinery is dead code.
//
// One warp owns 128 consecutive edges; lane owns 2 columns (float2): one
// warp gather = one 256B source row = 2 L2 lines. 8-deep unroll keeps 8
// independent gathers in flight. seg_ids sorted => interior segments of a
// chunk are exclusively owned by this warp: flush them with plain STG.64.
// Only the chunk's first segment and its final running segment can straddle
// warp boundaries -> those flush with atomicAdd.
//
// Inputs: 0 source[N,64] f32, 2 src_idx[E] i32, 3 seg_ids[E] i32 (sorted).

#define EDGES_PER_WARP 128

__global__ void zero_out_kernel(float4* __restrict__ out4, int n4) {
    int i = blockIdx.x * blockDim.x + threadIdx.x;
    int stride = gridDim.x * blockDim.x;
    for (int j = i; j < n4; j += stride)
        out4[j] = make_float4(0.f, 0.f, 0.f, 0.f);
}

__global__ void __launch_bounds__(256)
seg_gather_sum_kernel(const float2* __restrict__ src2,
                      const int4* __restrict__ src_idx4,
                      const int4* __restrict__ seg_ids4,
                      const int* __restrict__ src_idx,
                      const int* __restrict__ seg_ids,
                      float* __restrict__ out,
                      int E) {
    const int lane = threadIdx.x & 31;
    const int warp = blockIdx.x * (blockDim.x >> 5) + (threadIdx.x >> 5);
    int e0 = warp * EDGES_PER_WARP;
    if (e0 >= E) return;
    int e1 = e0 + EDGES_PER_WARP;
    if (e1 > E) e1 = E;

    const int first_seg = seg_ids[e0];
    int cur = first_seg;
    float ax = 0.f, ay = 0.f;

    int e = e0;
    int noct = (e1 - e0) >> 3;  // full 8-edge groups (e0 is 128-aligned)

    // Flush on segment change: the closed segment `cur` is interior
    // (exclusively ours) unless it is the chunk's first segment.
#define ACC(S, V)                                                       \
    do {                                                                \
        if ((S) != cur) {                                               \
            float2* p = (float2*)&out[(long long)cur * 64 + 2 * lane];  \
            if (cur == first_seg) {                                     \
                atomicAdd(&((float*)p)[0], ax);                         \
                atomicAdd(&((float*)p)[1], ay);                         \
            } else {                                                    \
                *p = make_float2(ax, ay);                               \
            }                                                           \
            ax = 0.f; ay = 0.f; cur = (S);                              \
        }                                                               \
        ax += (V).x; ay += (V).y;                                       \
    } while (0)

    for (int q = 0; q < noct; ++q, e += 8) {
        int4 sa = __ldg(&seg_ids4[(e >> 2) + 0]);
        int4 sb = __ldg(&seg_ids4[(e >> 2) + 1]);
        int4 ia = __ldg(&src_idx4[(e >> 2) + 0]);
        int4 ib = __ldg(&src_idx4[(e >> 2) + 1]);

        float2 v0 = __ldg(&src2[(long long)ia.x * 32 + lane]);
        float2 v1 = __ldg(&src2[(long long)ia.y * 32 + lane]);
        float2 v2 = __ldg(&src2[(long long)ia.z * 32 + lane]);
        float2 v3 = __ldg(&src2[(long long)ia.w * 32 + lane]);
        float2 v4 = __ldg(&src2[(long long)ib.x * 32 + lane]);
        float2 v5 = __ldg(&src2[(long long)ib.y * 32 + lane]);
        float2 v6 = __ldg(&src2[(long long)ib.z * 32 + lane]);
        float2 v7 = __ldg(&src2[(long long)ib.w * 32 + lane]);

        ACC(sa.x, v0);
        ACC(sa.y, v1);
        ACC(sa.z, v2);
        ACC(sa.w, v3);
        ACC(sb.x, v4);
        ACC(sb.y, v5);
        ACC(sb.z, v6);
        ACC(sb.w, v7);
    }

    // tail (only if E % 8 != 0 in the last chunk)
    for (; e < e1; ++e) {
        int s = __ldg(&seg_ids[e]);
        int idx = __ldg(&src_idx[e]);
        float2 v = __ldg(&src2[(long long)idx * 32 + lane]);
        ACC(s, v);
    }
#undef ACC

    // Final flush: the running segment may continue into the next chunk
    // (and may also be the first segment) -> always atomic.
    atomicAdd(&out[(long long)cur * 64 + 2 * lane + 0], ax);
    atomicAdd(&out[(long long)cur * 64 + 2 * lane + 1], ay);
}

extern "C" void kernel_launch(void* const* d_in, const int* in_sizes, int n_in,
                              void* d_out, int out_size) {
    const float* source  = (const float*)d_in[0];
    const int*   src_idx = (const int*)d_in[2];
    const int*   seg_ids = (const int*)d_in[3];
    float* out = (float*)d_out;

    int E = in_sizes[2];

    // 1) zero the output (poisoned by harness; empty segments must be 0)
    int n4 = out_size / 4;
    int zthreads = 256;
    int zblocks = (n4 + zthreads - 1) / zthreads;
    if (zblocks > 1184) zblocks = 1184;
    zero_out_kernel<<<zblocks, zthreads>>>((float4*)d_out, n4);

    // 2) gather + segment-sum
    int nwarps = (E + EDGES_PER_WARP - 1) / EDGES_PER_WARP;
    int threads = 256;  // 8 warps
    int nblocks = (nwarps + 7) / 8;
    seg_gather_sum_kernel<<<nblocks, threads>>>(
        (const float2*)source, (const int4*)src_idx, (const int4*)seg_ids,
        src_idx, seg_ids, out, E);
}